// round 6
// baseline (speedup 1.0000x reference)
#include <cuda_runtime.h>

#define T_STEPS 8192
#define N_CH    4096
#define DT      0.01f
#define L       64                    // time steps per chunk
#define KCHUNKS (T_STEPS / L)         // 128
#define CPB     128                   // threads per block
#define CHPB    256                   // channels per block (2 per thread, float2)
#define SLICES  (N_CH / CHPB)         // 16
#define NBLK    (KCHUNKS * SLICES)    // 2048 blocks per launch (single wave)
#define GENSH   11                    // log2(NBLK)
#define WIN     16                    // lookback window

// Scan state (no cudaMalloc -> __device__ globals). Never reset: flags are
// generation-tagged, so stale values from previous graph replays read "empty".
__device__ float    g_agg [KCHUNKS * N_CH];     // zero-start chunk aggregate
__device__ float    g_pref[KCHUNKS * N_CH];     // inclusive prefix (state at chunk end)
__device__ unsigned g_flag[KCHUNKS * SLICES];   // base+1=agg ready, base+2=pref ready
__device__ unsigned g_ticket;                   // monotone across launches

__device__ __forceinline__ float2 ldcg2(const float* p) {
    float2 v;
    asm volatile("ld.global.cg.v2.f32 {%0,%1}, [%2];" : "=f"(v.x), "=f"(v.y) : "l"(p));
    return v;
}
__device__ __forceinline__ void stcg2(float* p, float2 v) {
    asm volatile("st.global.cg.v2.f32 [%0], {%1,%2};" :: "l"(p), "f"(v.x), "f"(v.y));
}

__global__ void __launch_bounds__(CPB) scan_kernel(const float* __restrict__ x,
                                                   const float* __restrict__ tau,
                                                   const float* __restrict__ bias,
                                                   float* __restrict__ out) {
    __shared__ unsigned s_vid;
    __shared__ int      s_flag[WIN];
    const int tid = threadIdx.x;

    // Chunk-major ticket. Single wave: all 2048 CTAs are resident, so every
    // predecessor's aggregate gets published without any scheduling hazard.
    if (tid == 0) s_vid = atomicAdd(&g_ticket, 1u);
    __syncthreads();
    const unsigned gvid = s_vid;
    const unsigned base = (gvid >> GENSH) * 2u;   // generation tag
    const int vid   = (int)(gvid & (NBLK - 1));
    const int k     = vid / SLICES;               // chunk index (time)
    const int slice = vid % SLICES;               // channel slice
    const int j     = slice * CHPB + tid * 2;     // my channel pair

    const float2 tv = *reinterpret_cast<const float2*>(tau + j);
    const float a0 = DT / fmaxf(tv.x, DT), c0 = 1.0f - a0;
    const float a1 = DT / fmaxf(tv.y, DT), c1 = 1.0f - a1;
    float cl0 = c0, cl1 = c1;
#pragma unroll
    for (int p = 0; p < 6; ++p) { cl0 *= cl0; cl1 *= cl1; }   // c^64

    const float* xp = x + (size_t)k * L * N_CH + j;

    // ---- Phase 1: zero-start aggregate over my 64 rows (two indep chains) ----
    float g0 = 0.f, g1 = 0.f;
#pragma unroll
    for (int r = 0; r < L; ++r) {
        const float2 xv = *reinterpret_cast<const float2*>(xp + (size_t)r * N_CH);
        g0 = fmaf(c0, g0, a0 * xv.x);
        g1 = fmaf(c1, g1, a1 * xv.y);
    }

    float s0, s1;
    if (k == 0) {
        const float2 x0 = *reinterpret_cast<const float2*>(x + j);
        s0 = x0.x; s1 = x0.y;                       // s_0 = input[0, :]
        float2 pr; pr.x = fmaf(cl0, s0, g0); pr.y = fmaf(cl1, s1, g1);
        stcg2(&g_pref[j], pr);
        __syncthreads();
        if (tid == 0) { __threadfence(); atomicExch(&g_flag[slice], base + 2u); }
    } else {
        float2 ag; ag.x = g0; ag.y = g1;
        stcg2(&g_agg[(size_t)k * N_CH + j], ag);    // publish agg (never blocks)
        __syncthreads();
        if (tid == 0) { __threadfence(); atomicExch(&g_flag[k * SLICES + slice], base + 1u); }

        // ---- windowed decoupled lookback ----
        float cr0 = 0.f, cr1 = 0.f, f0 = 1.f, f1 = 1.f;
        int kk = k - 1;
        bool done = false;
        while (!done) {
            if (tid < WIN) {
                const int idx = kk - tid;
                unsigned f = 0u;
                if (idx >= 0) f = *(volatile unsigned*)&g_flag[idx * SLICES + slice];
                s_flag[tid] = (f > base) ? (int)(f - base) : 0;   // 0 empty, 1 agg, 2 pref
            }
            __syncthreads();
            int cnt = 0, d = -1;
#pragma unroll
            for (int i = 0; i < WIN; ++i) {
                const int f = s_flag[i];
                if (f == 0) break;
                cnt = i + 1;
                if (f == 2) { d = i; break; }
            }
            __syncthreads();
            if (cnt > 0) {
                __threadfence();   // acquire: order value loads after flag observation
                for (int i = 0; i < cnt; ++i) {
                    const float* src = (i == d) ? &g_pref[(size_t)(kk - i) * N_CH + j]
                                                : &g_agg [(size_t)(kk - i) * N_CH + j];
                    const float2 v = ldcg2(src);
                    cr0 = fmaf(f0, v.x, cr0);
                    cr1 = fmaf(f1, v.y, cr1);
                    if (i == d) { done = true; break; }
                    f0 *= cl0; f1 *= cl1;
                }
                kk -= cnt;
            }
        }
        s0 = cr0; s1 = cr1;

        float2 pr; pr.x = fmaf(cl0, s0, g0); pr.y = fmaf(cl1, s1, g1);
        stcg2(&g_pref[(size_t)k * N_CH + j], pr);
        __syncthreads();
        if (tid == 0) { __threadfence(); atomicExch(&g_flag[k * SLICES + slice], base + 2u); }
    }

    // ---- Phase 2: replay tile (x re-read hits L2), stream out ----
    const float2 bv = *reinterpret_cast<const float2*>(bias + j);
    float* op = out + (size_t)k * L * N_CH + j;
#pragma unroll
    for (int r = 0; r < L; ++r) {
        const float2 xv = *reinterpret_cast<const float2*>(xp + (size_t)r * N_CH);
        s0 = fmaf(c0, s0, a0 * xv.x);
        s1 = fmaf(c1, s1, a1 * xv.y);
        float2 o; o.x = s0 + bv.x; o.y = s1 + bv.y;
        *reinterpret_cast<float2*>(op + (size_t)r * N_CH) = o;
    }
}

extern "C" void kernel_launch(void* const* d_in, const int* in_sizes, int n_in,
                              void* d_out, int out_size) {
    const float* x    = (const float*)d_in[0];   // [T, N]
    const float* tau  = (const float*)d_in[1];   // [N]
    const float* bias = (const float*)d_in[2];   // [N]
    float*       out  = (float*)d_out;           // [T*N]

    scan_kernel<<<NBLK, CPB>>>(x, tau, bias, out);
}

// round 7
// speedup vs baseline: 1.2559x; 1.2559x over previous
#include <cuda_runtime.h>

#define T_STEPS 8192
#define N_CH    4096
#define DT      0.01f
#define L       64                    // time steps per chunk
#define KCHUNKS (T_STEPS / L)         // 128
#define CPB     256                   // threads per block = channels per block
#define SLICES  (N_CH / CPB)          // 16
#define NBLK    (KCHUNKS * SLICES)    // 2048 blocks per launch
#define GENSH   11                    // log2(NBLK)
#define WIN     16                    // lookback window

// Scan state (no cudaMalloc -> __device__ globals). Never reset: flags are
// generation-tagged, so stale values from previous graph replays read "empty".
__device__ float    g_agg [KCHUNKS * N_CH];     // zero-start chunk aggregate
__device__ float    g_pref[KCHUNKS * N_CH];     // inclusive prefix (state at chunk end)
__device__ unsigned g_flag[KCHUNKS * SLICES];   // base+1=agg ready, base+2=pref ready
__device__ unsigned g_ticket;                   // monotone across launches

__device__ __forceinline__ float ldcg(const float* p) {
    float v; asm volatile("ld.global.cg.f32 %0, [%1];" : "=f"(v) : "l"(p)); return v;
}
__device__ __forceinline__ void stcg(float* p, float v) {
    asm volatile("st.global.cg.f32 [%0], %1;" :: "l"(p), "f"(v));
}

__global__ void __launch_bounds__(CPB) scan_kernel(const float* __restrict__ x,
                                                   const float* __restrict__ tau,
                                                   const float* __restrict__ bias,
                                                   float* __restrict__ out) {
    __shared__ unsigned s_vid;
    __shared__ int      s_flag[WIN];
    const int tid = threadIdx.x;

    // Chunk-major ticket: every ticket-predecessor is resident-or-done, so
    // aggregates always get published -> lookback can never deadlock.
    if (tid == 0) s_vid = atomicAdd(&g_ticket, 1u);
    __syncthreads();
    const unsigned gvid = s_vid;
    const unsigned base = (gvid >> GENSH) * 2u;   // generation tag
    const int vid   = (int)(gvid & (NBLK - 1));
    const int k     = vid / SLICES;               // chunk index (time)
    const int slice = vid % SLICES;               // channel slice
    const int j     = slice * CPB + tid;          // my channel

    const float a = DT / fmaxf(tau[j], DT);
    const float c = 1.0f - a;
    float cl = c;
#pragma unroll
    for (int p = 0; p < 6; ++p) cl *= cl;         // c^64

    const float* xp = x + (size_t)k * L * N_CH + j;

    // ---- Phase 1: zero-start aggregate over my 64 rows ----
    float agg = 0.f;
#pragma unroll 16
    for (int r = 0; r < L; ++r)
        agg = fmaf(c, agg, a * xp[(size_t)r * N_CH]);

    float s_in;
    if (k == 0) {
        s_in = x[j];                              // s_0 = input[0, :]
        stcg(&g_pref[j], fmaf(cl, s_in, agg));
        __syncthreads();
        if (tid == 0) { __threadfence(); atomicExch(&g_flag[slice], base + 2u); }
    } else {
        stcg(&g_agg[(size_t)k * N_CH + j], agg);  // publish agg (never blocks)
        __syncthreads();
        if (tid == 0) { __threadfence(); atomicExch(&g_flag[k * SLICES + slice], base + 1u); }

        // ---- windowed decoupled lookback ----
        float carry = 0.f, factor = 1.f;
        int kk = k - 1;
        bool done = false;
        while (!done) {
            if (tid < WIN) {
                const int idx = kk - tid;
                unsigned f = 0u;
                if (idx >= 0) f = *(volatile unsigned*)&g_flag[idx * SLICES + slice];
                s_flag[tid] = (f > base) ? (int)(f - base) : 0;   // 0 empty, 1 agg, 2 pref
            }
            __syncthreads();
            int cnt = 0, d = -1;
#pragma unroll
            for (int i = 0; i < WIN; ++i) {
                const int f = s_flag[i];
                if (f == 0) break;
                cnt = i + 1;
                if (f == 2) { d = i; break; }
            }
            __syncthreads();
            if (cnt > 0) {
                __threadfence();   // acquire: order value loads after flag observation
                for (int i = 0; i < cnt; ++i) {
                    const float v = (i == d) ? ldcg(&g_pref[(size_t)(kk - i) * N_CH + j])
                                             : ldcg(&g_agg [(size_t)(kk - i) * N_CH + j]);
                    carry = fmaf(factor, v, carry);
                    if (i == d) { done = true; break; }
                    factor *= cl;
                }
                kk -= cnt;
            }
        }
        s_in = carry;

        stcg(&g_pref[(size_t)k * N_CH + j], fmaf(cl, s_in, agg));
        __syncthreads();
        if (tid == 0) { __threadfence(); atomicExch(&g_flag[k * SLICES + slice], base + 2u); }
    }

    // ---- Phase 2: replay tile from true s_in (x re-read hits L2), stream out ----
    const float b = bias[j];
    float s = s_in;
    float* op = out + (size_t)k * L * N_CH + j;
#pragma unroll 8
    for (int r = 0; r < L; ++r) {
        s = fmaf(c, s, a * xp[(size_t)r * N_CH]);
        op[(size_t)r * N_CH] = s + b;
    }
}

extern "C" void kernel_launch(void* const* d_in, const int* in_sizes, int n_in,
                              void* d_out, int out_size) {
    const float* x    = (const float*)d_in[0];   // [T, N]
    const float* tau  = (const float*)d_in[1];   // [N]
    const float* bias = (const float*)d_in[2];   // [N]
    float*       out  = (float*)d_out;           // [T*N]

    scan_kernel<<<NBLK, CPB>>>(x, tau, bias, out);
}